// round 6
// baseline (speedup 1.0000x reference)
#include <cuda_runtime.h>
#include <cuda_fp16.h>
#include <math.h>

#define BB   16
#define NN   1024
#define HH   4
#define KDIM 128
#define FO   64
#define COLS 256
#define ALPHA 0.2f
#define L2E   1.44269504088896340736f
#define MAXNZ 160

// Static device scratch
__device__ float  g_h[BB*NN*COLS];     // h fp32 (for k2), 16 MB
__device__ __half g_hh4[BB*NN*COLS];   // h fp16, head-interleaved per lane, 8 MB
__device__ float4 g_f1q[BB*NN], g_f2q[BB*NN];
__device__ float4 g_arq[BB*NN];        // alpha*log2e*(P_l^T f1)
__device__ float4 g_part[8][BB*NN];
__device__ float4 g_invq[BB*NN];

__device__ __forceinline__ float ex2f(float x) {
    float y; asm("ex2.approx.f32 %0, %1;" : "=f"(y) : "f"(x)); return y;
}
__device__ __forceinline__ void ffma2(unsigned long long& d,
                                      unsigned long long a, unsigned long long b) {
    asm("fma.rn.f32x2 %0, %1, %2, %0;" : "+l"(d) : "l"(a), "l"(b));
}
__device__ __forceinline__ float2 unpk(unsigned long long p) {
    float2 r;
    asm("mov.b64 {%0, %1}, %2;" : "=f"(r.x), "=f"(r.y) : "l"(p));
    return r;
}

// ---------------------------------------------------------------------------
// K1 v3: h = [x | SE] @ Wcat via FFMA2 packed ACROSS K (no packing movs).
// acc[r][c] = (sum over even k, sum over odd k); final = lo+hi.
// As[m][k] row-major (stride 36), Bs[c][k] col-major (stride 68):
// both operands load as ulonglong2 (LDS.128 -> 64-bit reg pairs) directly.
// Tile 128(M) x 64(N), 256 threads, 8x4 per thread. Grid (128, 4): ct = head.
// ---------------------------------------------------------------------------
__global__ void __launch_bounds__(256, 1) k1_gemm(
        const float* __restrict__ x, const float* __restrict__ SE,
        const float* __restrict__ W) {
    __shared__ __align__(16) float As[128][36];   // [m][k0..31], stride 144B
    __shared__ __align__(16) float Bs[64][68];    // [c][k0..31], stride 272B
    const int rt = blockIdx.x, ct = blockIdx.y, tid = threadIdx.x;
    const int tx = tid & 15, ty = tid >> 4;

    unsigned long long acc[8][4];
#pragma unroll
    for (int r = 0; r < 8; r++)
#pragma unroll
        for (int c = 0; c < 4; c++) acc[r][c] = 0ull;

    for (int ch = 0; ch < 4; ch++) {
        const int kk = ch * 32;
        // As: 128 m x 32 k  (row-major, k contiguous)
#pragma unroll
        for (int r = 0; r < 4; r++) {
            int q = tid + r * 256;
            int m = q >> 3, kc = (q & 7) << 2;
            int nb = rt * 128 + m;
            const float* src = (kk < 64)
                ? (x  + (size_t)nb * 64 + kk + kc)
                : (SE + (size_t)(nb & 1023) * 64 + (kk - 64) + kc);
            *(float4*)&As[m][kc] = *(const float4*)src;
        }
        // Bs: 64 c x 32 k (transposed from W; coalesced LDG.32, STS.128)
#pragma unroll
        for (int r = 0; r < 2; r++) {
            int q = tid + r * 256;
            int c = q & 63, k4 = (q >> 6) << 2;   // k4 in {0,4,8,12} (+16 for r=1)
            float4 v;
            const float* wp = W + ((size_t)ct * KDIM + kk + k4) * FO + c;
            v.x = wp[0]; v.y = wp[FO]; v.z = wp[2 * FO]; v.w = wp[3 * FO];
            *(float4*)&Bs[c][k4] = v;
        }
        __syncthreads();
#pragma unroll
        for (int kq = 0; kq < 8; kq++) {
            ulonglong2 bq[4];
#pragma unroll
            for (int c = 0; c < 4; c++)
                bq[c] = *(const ulonglong2*)&Bs[tx * 4 + c][kq * 4];
#pragma unroll
            for (int r = 0; r < 8; r++) {
                ulonglong2 aq = *(const ulonglong2*)&As[ty * 8 + r][kq * 4];
#pragma unroll
                for (int c = 0; c < 4; c++) {
                    ffma2(acc[r][c], aq.x, bq[c].x);
                    ffma2(acc[r][c], aq.y, bq[c].y);
                }
            }
        }
        __syncthreads();
    }
    // Epilogue: fp32 store + fp16 interleaved store
    const int row0 = rt * 128 + ty * 8;
#pragma unroll
    for (int r = 0; r < 8; r++) {
        float2 p0 = unpk(acc[r][0]);
        float2 p1 = unpk(acc[r][1]);
        float2 p2 = unpk(acc[r][2]);
        float2 p3 = unpk(acc[r][3]);
        float4 o = make_float4(p0.x + p0.y, p1.x + p1.y, p2.x + p2.y, p3.x + p3.y);
        size_t row = (size_t)(row0 + r);
        *(float4*)&g_h[row * COLS + ct * 64 + tx * 4] = o;
        __half2 q0 = __floats2half2_rn(o.x, o.y);
        __half2 q1 = __floats2half2_rn(o.z, o.w);
        __half2* dst = (__half2*)(g_hh4 + row * COLS);
        dst[(2 * tx) * 4 + ct]     = q0;
        dst[(2 * tx + 1) * 4 + ct] = q1;
    }
}

// ---------------------------------------------------------------------------
// K2: f1/f2 dot products + ar via 4-lane shfl.
// ---------------------------------------------------------------------------
__global__ void k2_f(const float* __restrict__ a1, const float* __restrict__ a2,
                     const float* __restrict__ P_l) {
    int t = blockIdx.x * 256 + threadIdx.x;       // B*N*H = 65536
    int h = t & 3, bi = t >> 2;
    const float4* hp  = (const float4*)(g_h + (size_t)bi * COLS + h * FO);
    const float4* a1p = (const float4*)(a1 + h * FO);
    const float4* a2p = (const float4*)(a2 + h * FO);
    float s1 = 0.f, s2 = 0.f;
#pragma unroll
    for (int k = 0; k < 16; k++) {
        float4 v = hp[k], w1 = a1p[k], w2 = a2p[k];
        s1 += v.x * w1.x + v.y * w1.y + v.z * w1.z + v.w * w1.w;
        s2 += v.x * w2.x + v.y * w2.y + v.z * w2.z + v.w * w2.w;
    }
    int lane = threadIdx.x & 31;
    int base = lane & ~3;
    float arv = 0.f;
#pragma unroll
    for (int hh = 0; hh < 4; hh++) {
        float f1h = __shfl_sync(0xffffffffu, s1, base + hh);
        arv = fmaf(P_l[hh * 4 + h], f1h, arv);
    }
    ((float*)g_f1q)[t] = s1;
    ((float*)g_f2q)[t] = s2;
    ((float*)g_arq)[t] = ALPHA * L2E * arv;
}

// ---------------------------------------------------------------------------
// K3: partial column sums  part[ic][b,j].g = sum_{i in chunk} exp2(e~_g(i,j))
// ---------------------------------------------------------------------------
__global__ void k3(const float* __restrict__ P_l) {
    const int ic = blockIdx.x, jt = blockIdx.y, b = blockIdx.z;
    __shared__ float4 sf1[128], sar[128];
    const int tid = threadIdx.x;
    if (tid < 128) sf1[tid]       = g_f1q[b * NN + ic * 128 + tid];
    else           sar[tid - 128] = g_arq[b * NN + ic * 128 + (tid - 128)];
    __syncthreads();

    const int j = jt * 256 + tid;
    const float4 f2 = g_f2q[b * NN + j];
    float c[16];
#pragma unroll
    for (int t = 0; t < 16; t++) c[t] = (1.f - ALPHA) * L2E * P_l[t];

    float s0 = 0.f, s1 = 0.f, s2 = 0.f, s3 = 0.f;
#pragma unroll 4
    for (int i = 0; i < 128; i++) {
        float4 f1 = sf1[i], ar = sar[i];
        float r0 = fmaxf(f1.x + f2.x, 0.f);
        float r1 = fmaxf(f1.y + f2.y, 0.f);
        float r2 = fmaxf(f1.z + f2.z, 0.f);
        float r3 = fmaxf(f1.w + f2.w, 0.f);
        float e0 = ar.x, e1 = ar.y, e2 = ar.z, e3 = ar.w;
        e0 = fmaf(c[0], r0, e0); e0 = fmaf(c[4], r1, e0); e0 = fmaf(c[8],  r2, e0); e0 = fmaf(c[12], r3, e0);
        e1 = fmaf(c[1], r0, e1); e1 = fmaf(c[5], r1, e1); e1 = fmaf(c[9],  r2, e1); e1 = fmaf(c[13], r3, e1);
        e2 = fmaf(c[2], r0, e2); e2 = fmaf(c[6], r1, e2); e2 = fmaf(c[10], r2, e2); e2 = fmaf(c[14], r3, e2);
        e3 = fmaf(c[3], r0, e3); e3 = fmaf(c[7], r1, e3); e3 = fmaf(c[11], r2, e3); e3 = fmaf(c[15], r3, e3);
        s0 += ex2f(e0); s1 += ex2f(e1); s2 += ex2f(e2); s3 += ex2f(e3);
    }
    g_part[ic][b * NN + j] = make_float4(s0, s1, s2, s3);
}

// K3b v2: 4 threads per (b,j), shfl-reduce, lane-0 writes reciprocals.
__global__ void k3b() {
    int t = blockIdx.x * 256 + threadIdx.x;   // 65536
    int bj = t >> 2, q = t & 3;
    float4 s = g_part[2 * q][bj];
    float4 p = g_part[2 * q + 1][bj];
    s.x += p.x; s.y += p.y; s.z += p.z; s.w += p.w;
#pragma unroll
    for (int d = 1; d < 4; d <<= 1) {
        s.x += __shfl_xor_sync(0xffffffffu, s.x, d);
        s.y += __shfl_xor_sync(0xffffffffu, s.y, d);
        s.z += __shfl_xor_sync(0xffffffffu, s.z, d);
        s.w += __shfl_xor_sync(0xffffffffu, s.w, d);
    }
    if (q == 0)
        g_invq[bj] = make_float4(1.f / s.x, 1.f / s.y, 1.f / s.z, 1.f / s.w);
}

// ---------------------------------------------------------------------------
// K4 v5: warp per row. Phase A preloads the full adj row (8 LDG.128, MLP 8)
// then ballots on registers. Phase C: interleaved fp16, 1 LDG.128/nnz.
// ---------------------------------------------------------------------------
__global__ void __launch_bounds__(256) k4(
        const float* __restrict__ x, const float* __restrict__ adj,
        const float* __restrict__ P_l, const float* __restrict__ P_w,
        float* __restrict__ out) {
    __shared__ int    sj[8][MAXNZ];
    __shared__ float4 sw[8][MAXNZ];
    const int ws   = threadIdx.x >> 5;
    const int lane = threadIdx.x & 31;
    const int gw   = blockIdx.x * 8 + ws;
    const int b = gw >> 10, i = gw & 1023;
    const int bN = b * NN;

    // Phase A: preload entire adj row, then register ballots
    const float* adjrow = adj + (size_t)(bN + i) * NN;
    float4 av[8];
#pragma unroll
    for (int q = 0; q < 8; q++)
        av[q] = *(const float4*)(adjrow + q * 128 + lane * 4);
    int base = 0;
#pragma unroll
    for (int q = 0; q < 8; q++) {
        float vv[4] = {av[q].x, av[q].y, av[q].z, av[q].w};
#pragma unroll
        for (int u = 0; u < 4; u++) {
            unsigned m = __ballot_sync(0xffffffffu, vv[u] != 0.f);
            if (vv[u] != 0.f) {
                int pos = base + __popc(m & ((1u << lane) - 1));
                if (pos < MAXNZ) sj[ws][pos] = q * 128 + lane * 4 + u;
            }
            base += __popc(m);
        }
    }
    int nnz = min(base, MAXNZ);
    __syncwarp();

    // Phase B: lane-parallel weights
    {
        const float4 f1 = g_f1q[bN + i];
        const float4 ar = g_arq[bN + i];
        float c[16], pw[16];
#pragma unroll
        for (int t = 0; t < 16; t++) { c[t] = (1.f - ALPHA) * L2E * P_l[t]; pw[t] = P_w[t]; }
        for (int t = lane; t < nnz; t += 32) {
            int j = sj[ws][t];
            float4 f2  = g_f2q[bN + j];
            float4 inv = g_invq[bN + j];
            float r0 = fmaxf(f1.x + f2.x, 0.f);
            float r1 = fmaxf(f1.y + f2.y, 0.f);
            float r2 = fmaxf(f1.z + f2.z, 0.f);
            float r3 = fmaxf(f1.w + f2.w, 0.f);
            float e0 = ar.x, e1 = ar.y, e2 = ar.z, e3 = ar.w;
            e0 = fmaf(c[0], r0, e0); e0 = fmaf(c[4], r1, e0); e0 = fmaf(c[8],  r2, e0); e0 = fmaf(c[12], r3, e0);
            e1 = fmaf(c[1], r0, e1); e1 = fmaf(c[5], r1, e1); e1 = fmaf(c[9],  r2, e1); e1 = fmaf(c[13], r3, e1);
            e2 = fmaf(c[2], r0, e2); e2 = fmaf(c[6], r1, e2); e2 = fmaf(c[10], r2, e2); e2 = fmaf(c[14], r3, e2);
            e3 = fmaf(c[3], r0, e3); e3 = fmaf(c[7], r1, e3); e3 = fmaf(c[11], r2, e3); e3 = fmaf(c[15], r3, e3);
            float x0 = ex2f(e0) * inv.x;
            float x1 = ex2f(e1) * inv.y;
            float x2 = ex2f(e2) * inv.z;
            float x3 = ex2f(e3) * inv.w;
            float w0 = pw[0]*x0 + pw[4]*x1 + pw[8]*x2  + pw[12]*x3;
            float w1 = pw[1]*x0 + pw[5]*x1 + pw[9]*x2  + pw[13]*x3;
            float w2 = pw[2]*x0 + pw[6]*x1 + pw[10]*x2 + pw[14]*x3;
            float w3 = pw[3]*x0 + pw[7]*x1 + pw[11]*x2 + pw[15]*x3;
            sw[ws][t] = make_float4(w0, w1, w2, w3);
        }
    }
    __syncwarp();

    // Phase C: interleaved fp16 gather, ONE LDG.128 per nnz, unroll 8
    float2 acc[4];
#pragma unroll
    for (int m = 0; m < 4; m++) acc[m] = make_float2(0.f, 0.f);

    const __half* hbase = g_hh4 + (size_t)bN * COLS + lane * 8;
    int t = 0;
    for (; t + 8 <= nnz; t += 8) {
#pragma unroll
        for (int u = 0; u < 8; u++) {
            int j = sj[ws][t + u];
            float4 w = sw[ws][t + u];
            uint4 u4 = *(const uint4*)(hbase + (size_t)j * COLS);
            float2 v0 = __half22float2(*(__half2*)&u4.x);
            float2 v1 = __half22float2(*(__half2*)&u4.y);
            float2 v2 = __half22float2(*(__half2*)&u4.z);
            float2 v3 = __half22float2(*(__half2*)&u4.w);
            acc[0].x = fmaf(w.x, v0.x, acc[0].x); acc[0].y = fmaf(w.x, v0.y, acc[0].y);
            acc[1].x = fmaf(w.y, v1.x, acc[1].x); acc[1].y = fmaf(w.y, v1.y, acc[1].y);
            acc[2].x = fmaf(w.z, v2.x, acc[2].x); acc[2].y = fmaf(w.z, v2.y, acc[2].y);
            acc[3].x = fmaf(w.w, v3.x, acc[3].x); acc[3].y = fmaf(w.w, v3.y, acc[3].y);
        }
    }
    for (; t < nnz; t++) {
        int j = sj[ws][t];
        float4 w = sw[ws][t];
        uint4 u4 = *(const uint4*)(hbase + (size_t)j * COLS);
        float2 v0 = __half22float2(*(__half2*)&u4.x);
        float2 v1 = __half22float2(*(__half2*)&u4.y);
        float2 v2 = __half22float2(*(__half2*)&u4.z);
        float2 v3 = __half22float2(*(__half2*)&u4.w);
        acc[0].x = fmaf(w.x, v0.x, acc[0].x); acc[0].y = fmaf(w.x, v0.y, acc[0].y);
        acc[1].x = fmaf(w.y, v1.x, acc[1].x); acc[1].y = fmaf(w.y, v1.y, acc[1].y);
        acc[2].x = fmaf(w.z, v2.x, acc[2].x); acc[2].y = fmaf(w.z, v2.y, acc[2].y);
        acc[3].x = fmaf(w.w, v3.x, acc[3].x); acc[3].y = fmaf(w.w, v3.y, acc[3].y);
    }

    // Epilogue: residual + ELU. Lane owns cols (h*64 + 2*lane, +1).
    float2 xv = *(const float2*)(x + (size_t)(bN + i) * FO + 2 * lane);
    float* orow = out + (size_t)(bN + i) * COLS;
#pragma unroll
    for (int m = 0; m < 4; m++) {
        float z0 = acc[m].x + xv.x;
        float z1 = acc[m].y + xv.y;
        float2 o;
        o.x = (z0 > 0.f) ? z0 : expm1f(z0);
        o.y = (z1 > 0.f) ? z1 : expm1f(z1);
        *(float2*)(orow + m * 64 + 2 * lane) = o;
    }
}

extern "C" void kernel_launch(void* const* d_in, const int* in_sizes, int n_in,
                              void* d_out, int out_size) {
    const float* x   = (const float*)d_in[0];
    const float* adj = (const float*)d_in[1];
    const float* SE  = (const float*)d_in[2];
    const float* W   = (const float*)d_in[3];
    const float* a1  = (const float*)d_in[4];
    const float* a2  = (const float*)d_in[5];
    const float* P_l = (const float*)d_in[6];
    const float* P_w = (const float*)d_in[7];
    float* out = (float*)d_out;

    k1_gemm<<<dim3(128, 4), 256>>>(x, SE, W);
    k2_f<<<256, 256>>>(a1, a2, P_l);
    k3<<<dim3(8, 4, 16), 256>>>(P_l);
    k3b<<<256, 256>>>();
    k4<<<2048, 256>>>(x, adj, P_l, P_w, out);
}

// round 7
// speedup vs baseline: 1.1839x; 1.1839x over previous
#include <cuda_runtime.h>
#include <cuda_fp16.h>
#include <math.h>

#define BB   16
#define NN   1024
#define HH   4
#define KDIM 128
#define FO   64
#define COLS 256
#define ALPHA 0.2f
#define L2E   1.44269504088896340736f
#define MAXNZ 160

// Static device scratch
__device__ float  g_h[BB*NN*COLS];     // h fp32 (for k2), 16 MB
__device__ __half g_hh4[BB*NN*COLS];   // h fp16, lane-interleaved for k4, 8 MB
// layout: halfs [row][lane(0..31)][h(0..3)][po(0..1)], value = h[row][h*64 + po*32 + lane]
__device__ float4 g_f1q[BB*NN], g_f2q[BB*NN];
__device__ float4 g_arq[BB*NN];        // alpha*log2e*(P_l^T f1)
__device__ float4 g_part[8][BB*NN];
__device__ float4 g_invq[BB*NN];

__device__ __forceinline__ float ex2f(float x) {
    float y; asm("ex2.approx.f32 %0, %1;" : "=f"(y) : "f"(x)); return y;
}
__device__ __forceinline__ void ffma2(unsigned long long& d,
                                      unsigned long long a, unsigned long long b) {
    asm("fma.rn.f32x2 %0, %1, %2, %0;" : "+l"(d) : "l"(a), "l"(b));
}
__device__ __forceinline__ float2 unpk(unsigned long long p) {
    float2 r;
    asm("mov.b64 {%0, %1}, %2;" : "=f"(r.x), "=f"(r.y) : "l"(p));
    return r;
}

// ---------------------------------------------------------------------------
// K1 v4: FFMA2 packed across K, CONFLICT-FREE banking.
// Thread (tx,ty) owns cols ct*64 + {tx, tx+16, tx+32, tx+48}, rows ty*8..+7.
// As[m][36] row-major k-contiguous; Bs[c][36] k-contiguous.
// B mainloop load Bs[tx+16c][kq*4]: bank start 4*tx -> 8 threads/phase tile
// all 32 banks (conflict-free). A load broadcast across tx.
// ---------------------------------------------------------------------------
__global__ void __launch_bounds__(256, 1) k1_gemm(
        const float* __restrict__ x, const float* __restrict__ SE,
        const float* __restrict__ W) {
    __shared__ __align__(16) float As[128][36];
    __shared__ __align__(16) float Bs[64][36];
    const int rt = blockIdx.x, ct = blockIdx.y, tid = threadIdx.x;
    const int tx = tid & 15, ty = tid >> 4;

    unsigned long long acc[8][4];
#pragma unroll
    for (int r = 0; r < 8; r++)
#pragma unroll
        for (int c = 0; c < 4; c++) acc[r][c] = 0ull;

    for (int ch = 0; ch < 4; ch++) {
        const int kk = ch * 32;
        // As: 128 m x 32 k (row-major, k contiguous)
#pragma unroll
        for (int r = 0; r < 4; r++) {
            int q = tid + r * 256;
            int m = q >> 3, kc = (q & 7) << 2;
            int nb = rt * 128 + m;
            const float* src = (kk < 64)
                ? (x  + (size_t)nb * 64 + kk + kc)
                : (SE + (size_t)(nb & 1023) * 64 + (kk - 64) + kc);
            *(float4*)&As[m][kc] = *(const float4*)src;
        }
        // Bs: 64 c x 32 k (transpose of W chunk; coalesced LDG.32, clean STS.128)
#pragma unroll
        for (int r = 0; r < 2; r++) {
            int q = tid + r * 256;
            int c = q & 63, k4 = (q >> 6) << 2;
            float4 v;
            const float* wp = W + ((size_t)ct * KDIM + kk + k4) * FO + c;
            v.x = wp[0]; v.y = wp[FO]; v.z = wp[2 * FO]; v.w = wp[3 * FO];
            *(float4*)&Bs[c][k4] = v;
        }
        __syncthreads();
#pragma unroll
        for (int kq = 0; kq < 8; kq++) {
            ulonglong2 bq[4];
#pragma unroll
            for (int c = 0; c < 4; c++)
                bq[c] = *(const ulonglong2*)&Bs[tx + 16 * c][kq * 4];
#pragma unroll
            for (int r = 0; r < 8; r++) {
                ulonglong2 aq = *(const ulonglong2*)&As[ty * 8 + r][kq * 4];
#pragma unroll
                for (int c = 0; c < 4; c++) {
                    ffma2(acc[r][c], aq.x, bq[c].x);
                    ffma2(acc[r][c], aq.y, bq[c].y);
                }
            }
        }
        __syncthreads();
    }
    // Epilogue. Thread's col c slot = ct*64 + tx + 16*c.
    const int row0 = rt * 128 + ty * 8;
#pragma unroll
    for (int r = 0; r < 8; r++) {
        float2 p0 = unpk(acc[r][0]);
        float2 p1 = unpk(acc[r][1]);
        float2 p2 = unpk(acc[r][2]);
        float2 p3 = unpk(acc[r][3]);
        float v0 = p0.x + p0.y;   // col tx
        float v1 = p1.x + p1.y;   // col tx+16
        float v2 = p2.x + p2.y;   // col tx+32
        float v3 = p3.x + p3.y;   // col tx+48
        size_t row = (size_t)(row0 + r);
        float* hro = g_h + row * COLS + ct * 64 + tx;
        hro[0] = v0; hro[16] = v1; hro[32] = v2; hro[48] = v3;
        // fp16 interleave: lane L owns (h=ct, po) pairs:
        //   col ct*64 + 0*32 + L  and  col ct*64 + 1*32 + L
        // cols tx (L=tx,po0), tx+32 (L=tx,po1)  -> half2 at [tx*4 + ct]
        // cols tx+16 (L=tx+16,po0), tx+48 (po1) -> half2 at [(tx+16)*4 + ct]
        __half2* dst = (__half2*)(g_hh4 + row * COLS);
        dst[tx * 4 + ct]        = __floats2half2_rn(v0, v2);
        dst[(tx + 16) * 4 + ct] = __floats2half2_rn(v1, v3);
    }
}

// ---------------------------------------------------------------------------
// K2: f1/f2 dot products + ar via 4-lane shfl.
// ---------------------------------------------------------------------------
__global__ void k2_f(const float* __restrict__ a1, const float* __restrict__ a2,
                     const float* __restrict__ P_l) {
    int t = blockIdx.x * 256 + threadIdx.x;       // B*N*H = 65536
    int h = t & 3, bi = t >> 2;
    const float4* hp  = (const float4*)(g_h + (size_t)bi * COLS + h * FO);
    const float4* a1p = (const float4*)(a1 + h * FO);
    const float4* a2p = (const float4*)(a2 + h * FO);
    float s1 = 0.f, s2 = 0.f;
#pragma unroll
    for (int k = 0; k < 16; k++) {
        float4 v = hp[k], w1 = a1p[k], w2 = a2p[k];
        s1 += v.x * w1.x + v.y * w1.y + v.z * w1.z + v.w * w1.w;
        s2 += v.x * w2.x + v.y * w2.y + v.z * w2.z + v.w * w2.w;
    }
    int lane = threadIdx.x & 31;
    int base = lane & ~3;
    float arv = 0.f;
#pragma unroll
    for (int hh = 0; hh < 4; hh++) {
        float f1h = __shfl_sync(0xffffffffu, s1, base + hh);
        arv = fmaf(P_l[hh * 4 + h], f1h, arv);
    }
    ((float*)g_f1q)[t] = s1;
    ((float*)g_f2q)[t] = s2;
    ((float*)g_arq)[t] = ALPHA * L2E * arv;
}

// ---------------------------------------------------------------------------
// K3: partial column sums  part[ic][b,j].g = sum_{i in chunk} exp2(e~_g(i,j))
// ---------------------------------------------------------------------------
__global__ void k3(const float* __restrict__ P_l) {
    const int ic = blockIdx.x, jt = blockIdx.y, b = blockIdx.z;
    __shared__ float4 sf1[128], sar[128];
    const int tid = threadIdx.x;
    if (tid < 128) sf1[tid]       = g_f1q[b * NN + ic * 128 + tid];
    else           sar[tid - 128] = g_arq[b * NN + ic * 128 + (tid - 128)];
    __syncthreads();

    const int j = jt * 256 + tid;
    const float4 f2 = g_f2q[b * NN + j];
    float c[16];
#pragma unroll
    for (int t = 0; t < 16; t++) c[t] = (1.f - ALPHA) * L2E * P_l[t];

    float s0 = 0.f, s1 = 0.f, s2 = 0.f, s3 = 0.f;
#pragma unroll 4
    for (int i = 0; i < 128; i++) {
        float4 f1 = sf1[i], ar = sar[i];
        float r0 = fmaxf(f1.x + f2.x, 0.f);
        float r1 = fmaxf(f1.y + f2.y, 0.f);
        float r2 = fmaxf(f1.z + f2.z, 0.f);
        float r3 = fmaxf(f1.w + f2.w, 0.f);
        float e0 = ar.x, e1 = ar.y, e2 = ar.z, e3 = ar.w;
        e0 = fmaf(c[0], r0, e0); e0 = fmaf(c[4], r1, e0); e0 = fmaf(c[8],  r2, e0); e0 = fmaf(c[12], r3, e0);
        e1 = fmaf(c[1], r0, e1); e1 = fmaf(c[5], r1, e1); e1 = fmaf(c[9],  r2, e1); e1 = fmaf(c[13], r3, e1);
        e2 = fmaf(c[2], r0, e2); e2 = fmaf(c[6], r1, e2); e2 = fmaf(c[10], r2, e2); e2 = fmaf(c[14], r3, e2);
        e3 = fmaf(c[3], r0, e3); e3 = fmaf(c[7], r1, e3); e3 = fmaf(c[11], r2, e3); e3 = fmaf(c[15], r3, e3);
        s0 += ex2f(e0); s1 += ex2f(e1); s2 += ex2f(e2); s3 += ex2f(e3);
    }
    g_part[ic][b * NN + j] = make_float4(s0, s1, s2, s3);
}

// K3b: serial reduce (measured faster than the shfl variant)
__global__ void k3b() {
    int bj = blockIdx.x * 256 + threadIdx.x;
    float4 s = g_part[0][bj];
#pragma unroll
    for (int ic = 1; ic < 8; ic++) {
        float4 p = g_part[ic][bj];
        s.x += p.x; s.y += p.y; s.z += p.z; s.w += p.w;
    }
    g_invq[bj] = make_float4(1.f / s.x, 1.f / s.y, 1.f / s.z, 1.f / s.w);
}

// ---------------------------------------------------------------------------
// K4: warp per row. Phase A: preloaded adj + register ballots.
// Phase C: lane L's uint4 = 4 half2, h-th pair = (col h*64+L, col h*64+32+L).
// ---------------------------------------------------------------------------
__global__ void __launch_bounds__(256) k4(
        const float* __restrict__ x, const float* __restrict__ adj,
        const float* __restrict__ P_l, const float* __restrict__ P_w,
        float* __restrict__ out) {
    __shared__ int    sj[8][MAXNZ];
    __shared__ float4 sw[8][MAXNZ];
    const int ws   = threadIdx.x >> 5;
    const int lane = threadIdx.x & 31;
    const int gw   = blockIdx.x * 8 + ws;
    const int b = gw >> 10, i = gw & 1023;
    const int bN = b * NN;

    // Phase A: preload entire adj row (MLP 8), then register ballots
    const float* adjrow = adj + (size_t)(bN + i) * NN;
    float4 av[8];
#pragma unroll
    for (int q = 0; q < 8; q++)
        av[q] = *(const float4*)(adjrow + q * 128 + lane * 4);
    int base = 0;
#pragma unroll
    for (int q = 0; q < 8; q++) {
        float vv[4] = {av[q].x, av[q].y, av[q].z, av[q].w};
#pragma unroll
        for (int u = 0; u < 4; u++) {
            unsigned m = __ballot_sync(0xffffffffu, vv[u] != 0.f);
            if (vv[u] != 0.f) {
                int pos = base + __popc(m & ((1u << lane) - 1));
                if (pos < MAXNZ) sj[ws][pos] = q * 128 + lane * 4 + u;
            }
            base += __popc(m);
        }
    }
    int nnz = min(base, MAXNZ);
    __syncwarp();

    // Phase B: lane-parallel weights
    {
        const float4 f1 = g_f1q[bN + i];
        const float4 ar = g_arq[bN + i];
        float c[16], pw[16];
#pragma unroll
        for (int t = 0; t < 16; t++) { c[t] = (1.f - ALPHA) * L2E * P_l[t]; pw[t] = P_w[t]; }
        for (int t = lane; t < nnz; t += 32) {
            int j = sj[ws][t];
            float4 f2  = g_f2q[bN + j];
            float4 inv = g_invq[bN + j];
            float r0 = fmaxf(f1.x + f2.x, 0.f);
            float r1 = fmaxf(f1.y + f2.y, 0.f);
            float r2 = fmaxf(f1.z + f2.z, 0.f);
            float r3 = fmaxf(f1.w + f2.w, 0.f);
            float e0 = ar.x, e1 = ar.y, e2 = ar.z, e3 = ar.w;
            e0 = fmaf(c[0], r0, e0); e0 = fmaf(c[4], r1, e0); e0 = fmaf(c[8],  r2, e0); e0 = fmaf(c[12], r3, e0);
            e1 = fmaf(c[1], r0, e1); e1 = fmaf(c[5], r1, e1); e1 = fmaf(c[9],  r2, e1); e1 = fmaf(c[13], r3, e1);
            e2 = fmaf(c[2], r0, e2); e2 = fmaf(c[6], r1, e2); e2 = fmaf(c[10], r2, e2); e2 = fmaf(c[14], r3, e2);
            e3 = fmaf(c[3], r0, e3); e3 = fmaf(c[7], r1, e3); e3 = fmaf(c[11], r2, e3); e3 = fmaf(c[15], r3, e3);
            float x0 = ex2f(e0) * inv.x;
            float x1 = ex2f(e1) * inv.y;
            float x2 = ex2f(e2) * inv.z;
            float x3 = ex2f(e3) * inv.w;
            float w0 = pw[0]*x0 + pw[4]*x1 + pw[8]*x2  + pw[12]*x3;
            float w1 = pw[1]*x0 + pw[5]*x1 + pw[9]*x2  + pw[13]*x3;
            float w2 = pw[2]*x0 + pw[6]*x1 + pw[10]*x2 + pw[14]*x3;
            float w3 = pw[3]*x0 + pw[7]*x1 + pw[11]*x2 + pw[15]*x3;
            sw[ws][t] = make_float4(w0, w1, w2, w3);
        }
    }
    __syncwarp();

    // Phase C: interleaved fp16 gather, ONE LDG.128 per nnz, unroll 8
    float2 acc[4];
#pragma unroll
    for (int m = 0; m < 4; m++) acc[m] = make_float2(0.f, 0.f);

    const __half* hbase = g_hh4 + (size_t)bN * COLS + lane * 8;
    int t = 0;
    for (; t + 8 <= nnz; t += 8) {
#pragma unroll
        for (int u = 0; u < 8; u++) {
            int j = sj[ws][t + u];
            float4 w = sw[ws][t + u];
            uint4 u4 = *(const uint4*)(hbase + (size_t)j * COLS);
            float2 v0 = __half22float2(*(__half2*)&u4.x);
            float2 v1 = __half22float2(*(__half2*)&u4.y);
            float2 v2 = __half22float2(*(__half2*)&u4.z);
            float2 v3 = __half22float2(*(__half2*)&u4.w);
            acc[0].x = fmaf(w.x, v0.x, acc[0].x); acc[0].y = fmaf(w.x, v0.y, acc[0].y);
            acc[1].x = fmaf(w.y, v1.x, acc[1].x); acc[1].y = fmaf(w.y, v1.y, acc[1].y);
            acc[2].x = fmaf(w.z, v2.x, acc[2].x); acc[2].y = fmaf(w.z, v2.y, acc[2].y);
            acc[3].x = fmaf(w.w, v3.x, acc[3].x); acc[3].y = fmaf(w.w, v3.y, acc[3].y);
        }
    }
    for (; t < nnz; t++) {
        int j = sj[ws][t];
        float4 w = sw[ws][t];
        uint4 u4 = *(const uint4*)(hbase + (size_t)j * COLS);
        float2 v0 = __half22float2(*(__half2*)&u4.x);
        float2 v1 = __half22float2(*(__half2*)&u4.y);
        float2 v2 = __half22float2(*(__half2*)&u4.z);
        float2 v3 = __half22float2(*(__half2*)&u4.w);
        acc[0].x = fmaf(w.x, v0.x, acc[0].x); acc[0].y = fmaf(w.x, v0.y, acc[0].y);
        acc[1].x = fmaf(w.y, v1.x, acc[1].x); acc[1].y = fmaf(w.y, v1.y, acc[1].y);
        acc[2].x = fmaf(w.z, v2.x, acc[2].x); acc[2].y = fmaf(w.z, v2.y, acc[2].y);
        acc[3].x = fmaf(w.w, v3.x, acc[3].x); acc[3].y = fmaf(w.w, v3.y, acc[3].y);
    }

    // Epilogue: residual + ELU. acc[h] = (col h*64+lane, col h*64+32+lane).
    const float* xrow = x + (size_t)(bN + i) * FO;
    float xv0 = xrow[lane], xv1 = xrow[lane + 32];
    float* orow = out + (size_t)(bN + i) * COLS;
#pragma unroll
    for (int m = 0; m < 4; m++) {
        float z0 = acc[m].x + xv0;
        float z1 = acc[m].y + xv1;
        orow[m * 64 + lane]      = (z0 > 0.f) ? z0 : expm1f(z0);
        orow[m * 64 + 32 + lane] = (z1 > 0.f) ? z1 : expm1f(z1);
    }
}

extern "C" void kernel_launch(void* const* d_in, const int* in_sizes, int n_in,
                              void* d_out, int out_size) {
    const float* x   = (const float*)d_in[0];
    const float* adj = (const float*)d_in[1];
    const float* SE  = (const float*)d_in[2];
    const float* W   = (const float*)d_in[3];
    const float* a1  = (const float*)d_in[4];
    const float* a2  = (const float*)d_in[5];
    const float* P_l = (const float*)d_in[6];
    const float* P_w = (const float*)d_in[7];
    float* out = (float*)d_out;

    k1_gemm<<<dim3(128, 4), 256>>>(x, SE, W);
    k2_f<<<256, 256>>>(a1, a2, P_l);
    k3<<<dim3(8, 4, 16), 256>>>(P_l);
    k3b<<<64, 256>>>();
    k4<<<2048, 256>>>(x, adj, P_l, P_w, out);
}